// round 3
// baseline (speedup 1.0000x reference)
#include <cuda_runtime.h>

#define LROW 2048
#define HID  128
#define KS   9
#define PAD  4
#define TPB  256
#define OPT  8            // outputs per thread: 256*8 = 2048 = one row per CTA
#define NP   (HID / 2)    // hidden pairs

typedef unsigned long long u64;

// Warp-uniform weights live in constant memory -> LDCU -> uniform registers.
__constant__ float2 cW1[KS * NP];   // (W1[k][2p], W1[k][2p+1])
__constant__ float2 cB1[NP];
__constant__ float2 cW2[NP];
__constant__ float  cB2;

#define PACK_F32X2(o, lo, hi) \
    asm("mov.b64 %0, {%1, %2};" : "=l"(o) : "f"(lo), "f"(hi))
#define UNPACK_F32X2(lo, hi, i) \
    asm("mov.b64 {%0, %1}, %2;" : "=f"(lo), "=f"(hi) : "l"(i))
#define FMA_F32X2(d, a, b, c) \
    asm("fma.rn.f32x2 %0, %1, %2, %3;" : "=l"(d) : "l"(a), "l"(b), "l"(c))

__global__ __launch_bounds__(TPB)
void simconv1d_kernel(const float* __restrict__ x, float* __restrict__ out)
{
    __shared__ __align__(16) float xs[LROW + 2 * PAD];

    const int row = blockIdx.x;          // b*64 + h
    const int tid = threadIdx.x;
    const float* xr = x + (size_t)row * LROW;

    // Stage x row into shared (vectorized), zero the halos.
    {
        const float4* x4  = (const float4*)xr;
        float4*       xs4 = (float4*)(xs + PAD);   // +4 floats = 16B, aligned
        #pragma unroll
        for (int i = tid; i < LROW / 4; i += TPB) xs4[i] = x4[i];
        if (tid < PAD) { xs[tid] = 0.0f; xs[LROW + PAD + tid] = 0.0f; }
    }
    __syncthreads();

    // Sliding window: outputs [o0, o0+8) need x[o0-4 .. o0+11] = xs[o0 .. o0+15].
    // Duplicate taps into packed (x, x) pairs ONCE — reused for all 64 d-pairs.
    const int o0 = tid * OPT;
    u64 xdup[OPT + KS - 1];
    #pragma unroll
    for (int i = 0; i < OPT + KS - 1; i++) {
        float v = xs[o0 + i];
        PACK_F32X2(xdup[i], v, v);
    }

    float y[OPT];
    #pragma unroll
    for (int j = 0; j < OPT; j++) y[j] = 0.0f;

    // Hidden units in packed pairs (d, d+1). Weights arrive via LDCU (uniform).
    #pragma unroll 1
    for (int p = 0; p < NP; p++) {
        u64 wp[KS];
        #pragma unroll
        for (int k = 0; k < KS; k++) {
            float2 w = cW1[k * NP + p];          // uniform const load
            PACK_F32X2(wp[k], w.x, w.y);
        }
        float2 bb = cB1[p];
        u64 b01;
        PACK_F32X2(b01, bb.x, bb.y);

        u64 hp[OPT];
        #pragma unroll
        for (int j = 0; j < OPT; j++) hp[j] = b01;

        #pragma unroll
        for (int k = 0; k < KS; k++) {
            #pragma unroll
            for (int j = 0; j < OPT; j++)
                FMA_F32X2(hp[j], xdup[j + k], wp[k], hp[j]);  // 2 FMA / instr
        }

        const float2 w2 = cW2[p];
        #pragma unroll
        for (int j = 0; j < OPT; j++) {
            float lo, hi;
            UNPACK_F32X2(lo, hi, hp[j]);
            y[j] = fmaf(fmaxf(lo, 0.0f), w2.x, y[j]);
            y[j] = fmaf(fmaxf(hi, 0.0f), w2.y, y[j]);
        }
    }

    float* orow = out + (size_t)row * LROW + o0;
    const float b2 = cB2;
    #pragma unroll
    for (int j = 0; j < OPT; j++) orow[j] = y[j] + b2;
}

extern "C" void kernel_launch(void* const* d_in, const int* in_sizes, int n_in,
                              void* d_out, int out_size)
{
    // d_in: x (8,64,2048) f32 | W1 (9,128) | b1 (128) | W2 (128,1) | b2 (1)
    cudaMemcpyToSymbolAsync(cW1, d_in[1], KS * HID * sizeof(float), 0,
                            cudaMemcpyDeviceToDevice, 0);
    cudaMemcpyToSymbolAsync(cB1, d_in[2], HID * sizeof(float), 0,
                            cudaMemcpyDeviceToDevice, 0);
    cudaMemcpyToSymbolAsync(cW2, d_in[3], HID * sizeof(float), 0,
                            cudaMemcpyDeviceToDevice, 0);
    cudaMemcpyToSymbolAsync(cB2, d_in[4], sizeof(float), 0,
                            cudaMemcpyDeviceToDevice, 0);

    simconv1d_kernel<<<8 * 64, TPB>>>((const float*)d_in[0], (float*)d_out);
}

// round 6
// speedup vs baseline: 1.1374x; 1.1374x over previous
#include <cuda_runtime.h>
#include <cstdint>

#define LROW 2048
#define HID  128
#define TPB  256          // 8 warps
#define NPASS 16          // 16 passes x 128 outputs = 2048 per CTA
#define XS_LEN 2080       // 4 left zero + 2048 + right zero pad
#define W1S 136           // padded row stride (136 % 32 == 8 -> conflict-free B loads)

typedef unsigned long long u64;

#define PACK_F32X2(o, lo, hi) \
    asm("mov.b64 %0, {%1, %2};" : "=l"(o) : "f"(lo), "f"(hi))
#define UNPACK_F32X2(lo, hi, i) \
    asm("mov.b64 {%0, %1}, %2;" : "=f"(lo), "=f"(hi) : "l"(i))
#define FMA_F32X2(d, a, b, c) \
    asm("fma.rn.f32x2 %0, %1, %2, %3;" : "=l"(d) : "l"(a), "l"(b), "l"(c))

// tf32 convert: destination is .b32 per PTX spec.
__device__ __forceinline__ uint32_t to_tf32(float v) {
    uint32_t r;
    asm("cvt.rna.tf32.f32 %0, %1;" : "=r"(r) : "f"(v));
    return r;
}

// tf32 MMA: A/B fragments are .b32 ("r"), accumulators .f32 ("f").
__device__ __forceinline__ void mma_tf32(
    float& d0, float& d1, float& d2, float& d3,
    uint32_t a0, uint32_t a1, uint32_t a2, uint32_t a3,
    uint32_t b0, uint32_t b1,
    float c0, float c1, float c2, float c3)
{
    asm("mma.sync.aligned.m16n8k8.row.col.f32.tf32.tf32.f32 "
        "{%0,%1,%2,%3}, {%4,%5,%6,%7}, {%8,%9}, {%10,%11,%12,%13};"
        : "=f"(d0), "=f"(d1), "=f"(d2), "=f"(d3)
        : "r"(a0), "r"(a1), "r"(a2), "r"(a3),
          "r"(b0), "r"(b1),
          "f"(c0), "f"(c1), "f"(c2), "f"(c3));
}

__global__ __launch_bounds__(TPB)
void simconv1d_mma(const float* __restrict__ x,
                   const float* __restrict__ W1,
                   const float* __restrict__ b1,
                   const float* __restrict__ W2,
                   const float* __restrict__ b2,
                   float* __restrict__ out)
{
    __shared__ __align__(16) uint32_t xs[XS_LEN];      // tf32-rounded padded row
    __shared__ __align__(16) uint32_t w1s[16 * W1S];   // tf32, rows 9..15 zero
    __shared__ __align__(8)  float b1s[HID];
    __shared__ __align__(8)  float w2s[HID];

    const int row = blockIdx.x;
    const int tid = threadIdx.x;
    const float* xr = x + (size_t)row * LROW;

    // Stage padded x row (tf32-rounded). xs[j] corresponds to x[j-4].
    for (int i = tid; i < XS_LEN; i += TPB) {
        uint32_t v = 0u;
        if (i >= 4 && i < 4 + LROW) v = to_tf32(xr[i - 4]);
        xs[i] = v;
    }
    // Stage W1 padded to 16 K-rows (tf32), zero rows 9..15 / cols >= 128.
    for (int i = tid; i < 16 * W1S; i += TPB) {
        int r = i / W1S, c = i % W1S;
        uint32_t v = (r < 9 && c < HID) ? to_tf32(W1[r * HID + c]) : 0u;
        w1s[i] = v;
    }
    if (tid < HID) { b1s[tid] = b1[tid]; w2s[tid] = W2[tid]; }
    __syncthreads();

    const int lane = tid & 31;
    const int warp = tid >> 5;
    const int g = lane >> 2;      // groupID (row within fragment)
    const int t = lane & 3;       // threadID_in_group
    const float b2v = b2[0];
    float* orow = out + (size_t)row * LROW;

    #pragma unroll 1
    for (int pass = 0; pass < NPASS; pass++) {
        const int o0p = pass * 128 + warp * 16;   // this warp's 16 outputs
        const int base = o0p + g + t;

        // Toeplitz A: A[m][k] = xs[o0p + m + k]. Both K-steps from 6 loads.
        const uint32_t a_0  = xs[base];
        const uint32_t a_4  = xs[base + 4];
        const uint32_t a_8  = xs[base + 8];
        const uint32_t a_12 = xs[base + 12];
        const uint32_t a_16 = xs[base + 16];
        const uint32_t a_20 = xs[base + 20];

        u64 y0p = 0ull, y1p = 0ull;   // packed partial sums, rows g and g+8

        #pragma unroll
        for (int n = 0; n < 16; n++) {
            const int nc = n * 8;
            // B fragments (col-major 8x8): b0 = W[k=t][nc+g], b1 = W[k=t+4][..]
            const uint32_t bk0_0 = w1s[t * W1S + nc + g];
            const uint32_t bk0_1 = w1s[(t + 4) * W1S + nc + g];
            const uint32_t bk1_0 = w1s[(t + 8) * W1S + nc + g];   // row 8 real, 9-11 zero
            const uint32_t bk1_1 = w1s[(t + 12) * W1S + nc + g];  // always zero rows

            const float2 bias = *(const float2*)&b1s[nc + 2 * t];  // cols 2t,2t+1

            float d0, d1, d2, d3;
            // K-step 0 (taps 0..7): bias injected as C operand — free.
            mma_tf32(d0, d1, d2, d3,
                     a_0, a_8, a_4, a_12,
                     bk0_0, bk0_1,
                     bias.x, bias.y, bias.x, bias.y);
            // K-step 1 (taps 8..15; 9..15 have zero weights).
            mma_tf32(d0, d1, d2, d3,
                     a_8, a_16, a_12, a_20,
                     bk1_0, bk1_1,
                     d0, d1, d2, d3);

            // Epilogue: relu then packed projection with W2.
            const float2 w2v = *(const float2*)&w2s[nc + 2 * t];
            u64 w2q; PACK_F32X2(w2q, w2v.x, w2v.y);
            float r0 = fmaxf(d0, 0.0f), r1 = fmaxf(d1, 0.0f);
            float r2 = fmaxf(d2, 0.0f), r3 = fmaxf(d3, 0.0f);
            u64 p01, p23;
            PACK_F32X2(p01, r0, r1);
            PACK_F32X2(p23, r2, r3);
            FMA_F32X2(y0p, p01, w2q, y0p);
            FMA_F32X2(y1p, p23, w2q, y1p);
        }

        // Horizontal: unpack, then reduce over the 4-thread quad (cols).
        float y0lo, y0hi, y1lo, y1hi;
        UNPACK_F32X2(y0lo, y0hi, y0p);
        UNPACK_F32X2(y1lo, y1hi, y1p);
        float y0 = y0lo + y0hi;
        float y1 = y1lo + y1hi;
        y0 += __shfl_xor_sync(0xffffffffu, y0, 1);
        y0 += __shfl_xor_sync(0xffffffffu, y0, 2);
        y1 += __shfl_xor_sync(0xffffffffu, y1, 1);
        y1 += __shfl_xor_sync(0xffffffffu, y1, 2);

        if (t == 0) {
            orow[o0p + g]     = y0 + b2v;
            orow[o0p + g + 8] = y1 + b2v;
        }
    }
}

extern "C" void kernel_launch(void* const* d_in, const int* in_sizes, int n_in,
                              void* d_out, int out_size)
{
    const float* x  = (const float*)d_in[0];  // (8, 64, 2048)
    const float* W1 = (const float*)d_in[1];  // (9, 128)
    const float* b1 = (const float*)d_in[2];  // (128,)
    const float* W2 = (const float*)d_in[3];  // (128, 1)
    const float* b2 = (const float*)d_in[4];  // (1,)
    float* out = (float*)d_out;               // (8, 64, 2048)

    simconv1d_mma<<<8 * 64, TPB>>>(x, W1, b1, W2, b2, out);
}

// round 8
// speedup vs baseline: 1.3399x; 1.1781x over previous
#include <cuda_runtime.h>
#include <cstdint>

#define LROW 2048
#define HID  128
#define TPB  256          // 8 warps
#define NPASS 16          // 16 passes x 128 outputs = 2048 per CTA
#define PCH  2            // passes per chunk (amortize B-fragment loads)
#define XS_LEN 2080       // 4 left zero + 2048 + right zero pad
#define W1S 136           // padded row stride (136 % 32 == 8 -> conflict-free)

typedef unsigned long long u64;

#define PACK_F32X2(o, lo, hi) \
    asm("mov.b64 %0, {%1, %2};" : "=l"(o) : "f"(lo), "f"(hi))
#define UNPACK_F32X2(lo, hi, i) \
    asm("mov.b64 {%0, %1}, %2;" : "=f"(lo), "=f"(hi) : "l"(i))
#define FMA_F32X2(d, a, b, c) \
    asm("fma.rn.f32x2 %0, %1, %2, %3;" : "=l"(d) : "l"(a), "l"(b), "l"(c))

__device__ __forceinline__ uint32_t to_tf32(float v) {
    uint32_t r;
    asm("cvt.rna.tf32.f32 %0, %1;" : "=r"(r) : "f"(v));
    return r;
}

__device__ __forceinline__ void mma_tf32(
    float& d0, float& d1, float& d2, float& d3,
    uint32_t a0, uint32_t a1, uint32_t a2, uint32_t a3,
    uint32_t b0, uint32_t b1,
    float c0, float c1, float c2, float c3)
{
    asm("mma.sync.aligned.m16n8k8.row.col.f32.tf32.tf32.f32 "
        "{%0,%1,%2,%3}, {%4,%5,%6,%7}, {%8,%9}, {%10,%11,%12,%13};"
        : "=f"(d0), "=f"(d1), "=f"(d2), "=f"(d3)
        : "r"(a0), "r"(a1), "r"(a2), "r"(a3),
          "r"(b0), "r"(b1),
          "f"(c0), "f"(c1), "f"(c2), "f"(c3));
}

__global__ __launch_bounds__(TPB, 2)   // cap regs at 128 -> 2 CTAs/SM
void simconv1d_mma(const float* __restrict__ x,
                   const float* __restrict__ W1,
                   const float* __restrict__ b1,
                   const float* __restrict__ W2,
                   const float* __restrict__ b2,
                   float* __restrict__ out)
{
    __shared__ __align__(16) uint32_t xs[XS_LEN];      // tf32-rounded padded row
    __shared__ __align__(16) uint32_t w1s[16 * W1S];   // tf32, rows 9..15 zero
    __shared__ __align__(8)  float b1s[HID];
    __shared__ __align__(8)  float w2s[HID];

    const int row = blockIdx.x;
    const int tid = threadIdx.x;
    const float* xr = x + (size_t)row * LROW;

    // Stage padded x row (tf32-rounded). xs[j] corresponds to x[j-4].
    for (int i = tid; i < XS_LEN; i += TPB) {
        uint32_t v = 0u;
        if (i >= 4 && i < 4 + LROW) v = to_tf32(xr[i - 4]);
        xs[i] = v;
    }
    // Stage W1 padded to 16 K-rows (tf32), zero rows 9..15 / cols >= 128.
    for (int i = tid; i < 16 * W1S; i += TPB) {
        int r = i / W1S, c = i % W1S;
        w1s[i] = (r < 9 && c < HID) ? to_tf32(W1[r * HID + c]) : 0u;
    }
    if (tid < HID) { b1s[tid] = b1[tid]; w2s[tid] = W2[tid]; }
    __syncthreads();

    const int lane = tid & 31;
    const int warp = tid >> 5;
    const int g = lane >> 2;      // groupID (row within fragment)
    const int t = lane & 3;       // threadID_in_group
    const float b2v = b2[0];
    float* orow = out + (size_t)row * LROW;

    #pragma unroll 1
    for (int pc = 0; pc < NPASS / PCH; pc++) {
        // This chunk covers PCH passes; warp's outputs per pass are 16 wide.
        int o0p[PCH];
        uint32_t A[PCH][6];
        u64 y0p[PCH], y1p[PCH];
        #pragma unroll
        for (int q = 0; q < PCH; q++) {
            o0p[q] = (pc * PCH + q) * 128 + warp * 16;
            const int base = o0p[q] + g + t;
            // Toeplitz A: A[m][k] = xs[o0p + m + k]; both K-steps from 6 loads.
            A[q][0] = xs[base];
            A[q][1] = xs[base + 4];
            A[q][2] = xs[base + 8];
            A[q][3] = xs[base + 12];
            A[q][4] = xs[base + 16];
            A[q][5] = xs[base + 20];
            y0p[q] = 0ull;
            y1p[q] = 0ull;
        }

        #pragma unroll 4
        for (int n = 0; n < 16; n++) {
            const int nc = n * 8;
            // B fragments (col-major 8x8), shared across the PCH passes.
            const uint32_t bk0_0 = w1s[t * W1S + nc + g];
            const uint32_t bk0_1 = w1s[(t + 4) * W1S + nc + g];
            const uint32_t bk1_0 = w1s[(t + 8) * W1S + nc + g];  // row 8 real, rest 0
            const uint32_t bk1_1 = w1s[(t + 12) * W1S + nc + g]; // all zero rows

            const float2 bias = *(const float2*)&b1s[nc + 2 * t];
            const float2 w2v  = *(const float2*)&w2s[nc + 2 * t];
            u64 w2q; PACK_F32X2(w2q, w2v.x, w2v.y);

            #pragma unroll
            for (int q = 0; q < PCH; q++) {
                float d0, d1, d2, d3;
                // K-step 0 (taps 0..7): bias injected as C — free.
                mma_tf32(d0, d1, d2, d3,
                         A[q][0], A[q][2], A[q][1], A[q][3],
                         bk0_0, bk0_1,
                         bias.x, bias.y, bias.x, bias.y);
                // K-step 1 (taps 8..15; 9..15 zero weights).
                mma_tf32(d0, d1, d2, d3,
                         A[q][2], A[q][4], A[q][3], A[q][5],
                         bk1_0, bk1_1,
                         d0, d1, d2, d3);

                // relu + packed projection with W2.
                float r0 = fmaxf(d0, 0.0f), r1 = fmaxf(d1, 0.0f);
                float r2 = fmaxf(d2, 0.0f), r3 = fmaxf(d3, 0.0f);
                u64 p01, p23;
                PACK_F32X2(p01, r0, r1);
                PACK_F32X2(p23, r2, r3);
                FMA_F32X2(y0p[q], p01, w2q, y0p[q]);
                FMA_F32X2(y1p[q], p23, w2q, y1p[q]);
            }
        }

        #pragma unroll
        for (int q = 0; q < PCH; q++) {
            float y0lo, y0hi, y1lo, y1hi;
            UNPACK_F32X2(y0lo, y0hi, y0p[q]);
            UNPACK_F32X2(y1lo, y1hi, y1p[q]);
            float y0 = y0lo + y0hi;
            float y1 = y1lo + y1hi;
            y0 += __shfl_xor_sync(0xffffffffu, y0, 1);
            y0 += __shfl_xor_sync(0xffffffffu, y0, 2);
            y1 += __shfl_xor_sync(0xffffffffu, y1, 1);
            y1 += __shfl_xor_sync(0xffffffffu, y1, 2);
            if (t == 0) {
                orow[o0p[q] + g]     = y0 + b2v;
                orow[o0p[q] + g + 8] = y1 + b2v;
            }
        }
    }
}

extern "C" void kernel_launch(void* const* d_in, const int* in_sizes, int n_in,
                              void* d_out, int out_size)
{
    const float* x  = (const float*)d_in[0];  // (8, 64, 2048)
    const float* W1 = (const float*)d_in[1];  // (9, 128)
    const float* b1 = (const float*)d_in[2];  // (128,)
    const float* W2 = (const float*)d_in[3];  // (128, 1)
    const float* b2 = (const float*)d_in[4];  // (1,)
    float* out = (float*)d_out;               // (8, 64, 2048)

    simconv1d_mma<<<8 * 64, TPB>>>(x, W1, b1, W2, b2, out);
}

// round 9
// speedup vs baseline: 1.3946x; 1.0409x over previous
#include <cuda_runtime.h>
#include <cstdint>

#define LROW 2048
#define HALF 1024         // outputs per CTA (row split in 2)
#define HID  128
#define TPB  128          // 4 warps
#define NPASS 16          // 16 passes x 64 outputs = 1024 per CTA
#define PCH  2            // passes per chunk (amortize B-fragment loads)
#define XS_LEN 1040       // 4 halo + 1024 + 4 halo + align pad
#define W1S 136           // padded row stride (136 % 32 == 8 -> conflict-free)

typedef unsigned long long u64;

#define PACK_F32X2(o, lo, hi) \
    asm("mov.b64 %0, {%1, %2};" : "=l"(o) : "f"(lo), "f"(hi))
#define UNPACK_F32X2(lo, hi, i) \
    asm("mov.b64 {%0, %1}, %2;" : "=f"(lo), "=f"(hi) : "l"(i))
#define FMA_F32X2(d, a, b, c) \
    asm("fma.rn.f32x2 %0, %1, %2, %3;" : "=l"(d) : "l"(a), "l"(b), "l"(c))

__device__ __forceinline__ uint32_t to_tf32(float v) {
    uint32_t r;
    asm("cvt.rna.tf32.f32 %0, %1;" : "=r"(r) : "f"(v));
    return r;
}

__device__ __forceinline__ void mma_tf32(
    float& d0, float& d1, float& d2, float& d3,
    uint32_t a0, uint32_t a1, uint32_t a2, uint32_t a3,
    uint32_t b0, uint32_t b1,
    float c0, float c1, float c2, float c3)
{
    asm("mma.sync.aligned.m16n8k8.row.col.f32.tf32.tf32.f32 "
        "{%0,%1,%2,%3}, {%4,%5,%6,%7}, {%8,%9}, {%10,%11,%12,%13};"
        : "=f"(d0), "=f"(d1), "=f"(d2), "=f"(d3)
        : "r"(a0), "r"(a1), "r"(a2), "r"(a3),
          "r"(b0), "r"(b1),
          "f"(c0), "f"(c1), "f"(c2), "f"(c3));
}

__global__ __launch_bounds__(TPB, 6)   // cap regs at 85 -> 6 CTAs/SM (24 warps)
void simconv1d_mma(const float* __restrict__ x,
                   const float* __restrict__ W1,
                   const float* __restrict__ b1,
                   const float* __restrict__ W2,
                   const float* __restrict__ b2,
                   float* __restrict__ out)
{
    __shared__ __align__(16) uint32_t xs[XS_LEN];      // tf32 padded half-row
    __shared__ __align__(16) uint32_t w1s[16 * W1S];   // tf32, rows 9..15 zero
    __shared__ __align__(8)  float b1s[HID];
    __shared__ __align__(8)  float w2s[HID];

    const int row  = blockIdx.x >> 1;       // b*64 + h
    const int h0   = (blockIdx.x & 1) * HALF;  // output offset within row
    const int tid  = threadIdx.x;
    const float* xr = x + (size_t)row * LROW;

    // Stage padded x segment (tf32). xs[j] corresponds to x[h0 + j - 4].
    for (int i = tid; i < HALF + 8; i += TPB) {
        const int gidx = h0 + i - 4;
        uint32_t v = 0u;
        if (gidx >= 0 && gidx < LROW) v = to_tf32(xr[gidx]);
        xs[i] = v;
    }
    // Stage W1 padded to 16 K-rows (tf32), zero rows 9..15 / cols >= 128.
    for (int i = tid; i < 16 * W1S; i += TPB) {
        int r = i / W1S, c = i % W1S;
        w1s[i] = (r < 9 && c < HID) ? to_tf32(W1[r * HID + c]) : 0u;
    }
    if (tid < HID) { b1s[tid] = b1[tid]; w2s[tid] = W2[tid]; }
    __syncthreads();

    const int lane = tid & 31;
    const int warp = tid >> 5;
    const int g = lane >> 2;      // groupID (row within fragment)
    const int t = lane & 3;       // threadID_in_group
    const float b2v = b2[0];
    float* orow = out + (size_t)row * LROW + h0;

    #pragma unroll 1
    for (int pc = 0; pc < NPASS / PCH; pc++) {
        // This chunk covers PCH passes; warp's outputs per pass are 16 wide.
        int o0p[PCH];
        uint32_t A[PCH][6];
        u64 y0p[PCH], y1p[PCH];
        #pragma unroll
        for (int q = 0; q < PCH; q++) {
            o0p[q] = (pc * PCH + q) * 64 + warp * 16;   // local to the half-row
            const int base = o0p[q] + g + t;
            // Toeplitz A: A[m][k] = xs[o0p + m + k]; both K-steps from 6 loads.
            A[q][0] = xs[base];
            A[q][1] = xs[base + 4];
            A[q][2] = xs[base + 8];
            A[q][3] = xs[base + 12];
            A[q][4] = xs[base + 16];
            A[q][5] = xs[base + 20];
            y0p[q] = 0ull;
            y1p[q] = 0ull;
        }

        #pragma unroll 4
        for (int n = 0; n < 16; n++) {
            const int nc = n * 8;
            // B fragments (col-major 8x8), shared across the PCH passes.
            const uint32_t bk0_0 = w1s[t * W1S + nc + g];
            const uint32_t bk0_1 = w1s[(t + 4) * W1S + nc + g];
            const uint32_t bk1_0 = w1s[(t + 8) * W1S + nc + g];  // row 8 real, rest 0
            const uint32_t bk1_1 = w1s[(t + 12) * W1S + nc + g]; // all zero rows

            const float2 bias = *(const float2*)&b1s[nc + 2 * t];
            const float2 w2v  = *(const float2*)&w2s[nc + 2 * t];
            u64 w2q; PACK_F32X2(w2q, w2v.x, w2v.y);

            #pragma unroll
            for (int q = 0; q < PCH; q++) {
                float d0, d1, d2, d3;
                // K-step 0 (taps 0..7): bias injected as C — free.
                mma_tf32(d0, d1, d2, d3,
                         A[q][0], A[q][2], A[q][1], A[q][3],
                         bk0_0, bk0_1,
                         bias.x, bias.y, bias.x, bias.y);
                // K-step 1 (taps 8..15; 9..15 zero weights).
                mma_tf32(d0, d1, d2, d3,
                         A[q][2], A[q][4], A[q][3], A[q][5],
                         bk1_0, bk1_1,
                         d0, d1, d2, d3);

                // relu + packed projection with W2.
                float r0 = fmaxf(d0, 0.0f), r1 = fmaxf(d1, 0.0f);
                float r2 = fmaxf(d2, 0.0f), r3 = fmaxf(d3, 0.0f);
                u64 p01, p23;
                PACK_F32X2(p01, r0, r1);
                PACK_F32X2(p23, r2, r3);
                FMA_F32X2(y0p[q], p01, w2q, y0p[q]);
                FMA_F32X2(y1p[q], p23, w2q, y1p[q]);
            }
        }

        #pragma unroll
        for (int q = 0; q < PCH; q++) {
            float y0lo, y0hi, y1lo, y1hi;
            UNPACK_F32X2(y0lo, y0hi, y0p[q]);
            UNPACK_F32X2(y1lo, y1hi, y1p[q]);
            float y0 = y0lo + y0hi;
            float y1 = y1lo + y1hi;
            y0 += __shfl_xor_sync(0xffffffffu, y0, 1);
            y0 += __shfl_xor_sync(0xffffffffu, y0, 2);
            y1 += __shfl_xor_sync(0xffffffffu, y1, 1);
            y1 += __shfl_xor_sync(0xffffffffu, y1, 2);
            if (t == 0) {
                orow[o0p[q] + g]     = y0 + b2v;
                orow[o0p[q] + g + 8] = y1 + b2v;
            }
        }
    }
}

extern "C" void kernel_launch(void* const* d_in, const int* in_sizes, int n_in,
                              void* d_out, int out_size)
{
    const float* x  = (const float*)d_in[0];  // (8, 64, 2048)
    const float* W1 = (const float*)d_in[1];  // (9, 128)
    const float* b1 = (const float*)d_in[2];  // (128,)
    const float* W2 = (const float*)d_in[3];  // (128, 1)
    const float* b2 = (const float*)d_in[4];  // (1,)
    float* out = (float*)d_out;               // (8, 64, 2048)

    simconv1d_mma<<<8 * 64 * 2, TPB>>>(x, W1, b1, W2, b2, out);
}

// round 11
// speedup vs baseline: 1.4035x; 1.0064x over previous
#include <cuda_runtime.h>
#include <cstdint>

#define LROW 2048
#define HALF 1024         // outputs per CTA (row split in 2)
#define HID  128
#define TPB  128          // 4 warps
#define NPASS 16          // 16 passes x 64 outputs = 1024 per CTA
#define PCH  4            // passes per chunk (amortize B-frag loads, 4x ILP)
#define XS_LEN 1040       // 4 halo + 1024 + 4 halo + align pad
#define W1S 136           // padded row stride (136 % 32 == 8 -> conflict-free)

typedef unsigned long long u64;

#define PACK_F32X2(o, lo, hi) \
    asm("mov.b64 %0, {%1, %2};" : "=l"(o) : "f"(lo), "f"(hi))
#define UNPACK_F32X2(lo, hi, i) \
    asm("mov.b64 {%0, %1}, %2;" : "=f"(lo), "=f"(hi) : "l"(i))
#define FMA_F32X2(d, a, b, c) \
    asm("fma.rn.f32x2 %0, %1, %2, %3;" : "=l"(d) : "l"(a), "l"(b), "l"(c))

__device__ __forceinline__ uint32_t to_tf32(float v) {
    uint32_t r;
    asm("cvt.rna.tf32.f32 %0, %1;" : "=r"(r) : "f"(v));
    return r;
}

__device__ __forceinline__ void mma_tf32(
    float& d0, float& d1, float& d2, float& d3,
    uint32_t a0, uint32_t a1, uint32_t a2, uint32_t a3,
    uint32_t b0, uint32_t b1,
    float c0, float c1, float c2, float c3)
{
    asm("mma.sync.aligned.m16n8k8.row.col.f32.tf32.tf32.f32 "
        "{%0,%1,%2,%3}, {%4,%5,%6,%7}, {%8,%9}, {%10,%11,%12,%13};"
        : "=f"(d0), "=f"(d1), "=f"(d2), "=f"(d3)
        : "r"(a0), "r"(a1), "r"(a2), "r"(a3),
          "r"(b0), "r"(b1),
          "f"(c0), "f"(c1), "f"(c2), "f"(c3));
}

__global__ __launch_bounds__(TPB, 5)   // 102-reg cap -> 5 CTAs/SM (20 warps)
void simconv1d_mma(const float* __restrict__ x,
                   const float* __restrict__ W1,
                   const float* __restrict__ b1,
                   const float* __restrict__ W2,
                   const float* __restrict__ b2,
                   float* __restrict__ out)
{
    __shared__ __align__(16) uint32_t xs[XS_LEN];      // tf32 padded half-row
    __shared__ __align__(16) uint32_t w1s[16 * W1S];   // tf32, rows 9..15 zero
    __shared__ __align__(8)  float b1s[HID];
    __shared__ __align__(8)  u64   w2q_s[HID / 2];     // pre-packed (w2[2t],w2[2t+1])

    const int row  = blockIdx.x >> 1;          // b*64 + h
    const int h0   = (blockIdx.x & 1) * HALF;  // output offset within row
    const int tid  = threadIdx.x;
    const float* xr = x + (size_t)row * LROW;

    // Stage padded x segment (tf32). xs[j] corresponds to x[h0 + j - 4].
    for (int i = tid; i < HALF + 8; i += TPB) {
        const int gidx = h0 + i - 4;
        uint32_t v = 0u;
        if (gidx >= 0 && gidx < LROW) v = to_tf32(xr[gidx]);
        xs[i] = v;
    }
    // Stage W1 padded to 16 K-rows (tf32), zero rows 9..15 / cols >= 128.
    for (int i = tid; i < 16 * W1S; i += TPB) {
        int r = i / W1S, c = i % W1S;
        w1s[i] = (r < 9 && c < HID) ? to_tf32(W1[r * HID + c]) : 0u;
    }
    if (tid < HID) b1s[tid] = b1[tid];
    if (tid < HID / 2) {                        // pre-pack W2 pairs
        u64 wq;
        PACK_F32X2(wq, W2[2 * tid], W2[2 * tid + 1]);
        w2q_s[tid] = wq;
    }
    __syncthreads();

    const int lane = tid & 31;
    const int warp = tid >> 5;
    const int g = lane >> 2;      // groupID (row within fragment)
    const int t = lane & 3;       // threadID_in_group
    const float b2v = b2[0];
    float* orow = out + (size_t)row * LROW + h0;

    #pragma unroll 1
    for (int pc = 0; pc < NPASS / PCH; pc++) {
        int o0p[PCH];
        uint32_t A[PCH][6];
        u64 y0p[PCH], y1p[PCH];
        #pragma unroll
        for (int q = 0; q < PCH; q++) {
            o0p[q] = (pc * PCH + q) * 64 + warp * 16;   // local to half-row
            const int base = o0p[q] + g + t;
            // Toeplitz A: A[m][k] = xs[o0p + m + k]; both K-steps from 6 loads.
            A[q][0] = xs[base];
            A[q][1] = xs[base + 4];
            A[q][2] = xs[base + 8];
            A[q][3] = xs[base + 12];
            A[q][4] = xs[base + 16];
            A[q][5] = xs[base + 20];
            y0p[q] = 0ull;
            y1p[q] = 0ull;
        }

        #pragma unroll 2
        for (int n = 0; n < 16; n++) {
            const int nc = n * 8;
            // B fragments (col-major 8x8), shared across the PCH passes.
            const uint32_t bk0_0 = w1s[t * W1S + nc + g];
            const uint32_t bk0_1 = w1s[(t + 4) * W1S + nc + g];
            const uint32_t bk1_0 = w1s[(t + 8) * W1S + nc + g];  // row 8 real, rest 0
            const uint32_t bk1_1 = w1s[(t + 12) * W1S + nc + g]; // all zero rows

            const float2 bias = *(const float2*)&b1s[nc + 2 * t];
            const u64 w2q = w2q_s[(nc + 2 * t) >> 1];            // pre-packed

            #pragma unroll
            for (int q = 0; q < PCH; q++) {
                float d0, d1, d2, d3;
                // K-step 0 (taps 0..7): bias injected as C — free.
                mma_tf32(d0, d1, d2, d3,
                         A[q][0], A[q][2], A[q][1], A[q][3],
                         bk0_0, bk0_1,
                         bias.x, bias.y, bias.x, bias.y);
                // K-step 1 (taps 8..15; 9..15 zero weights).
                mma_tf32(d0, d1, d2, d3,
                         A[q][2], A[q][4], A[q][3], A[q][5],
                         bk1_0, bk1_1,
                         d0, d1, d2, d3);

                // relu + packed projection with W2.
                float r0 = fmaxf(d0, 0.0f), r1 = fmaxf(d1, 0.0f);
                float r2 = fmaxf(d2, 0.0f), r3 = fmaxf(d3, 0.0f);
                u64 p01, p23;
                PACK_F32X2(p01, r0, r1);
                PACK_F32X2(p23, r2, r3);
                FMA_F32X2(y0p[q], p01, w2q, y0p[q]);
                FMA_F32X2(y1p[q], p23, w2q, y1p[q]);
            }
        }

        #pragma unroll
        for (int q = 0; q < PCH; q++) {
            float y0lo, y0hi, y1lo, y1hi;
            UNPACK_F32X2(y0lo, y0hi, y0p[q]);
            UNPACK_F32X2(y1lo, y1hi, y1p[q]);
            float y0 = y0lo + y0hi;
            float y1 = y1lo + y1hi;
            y0 += __shfl_xor_sync(0xffffffffu, y0, 1);
            y0 += __shfl_xor_sync(0xffffffffu, y0, 2);
            y1 += __shfl_xor_sync(0xffffffffu, y1, 1);
            y1 += __shfl_xor_sync(0xffffffffu, y1, 2);
            if (t == 0) {
                orow[o0p[q] + g]     = y0 + b2v;
                orow[o0p[q] + g + 8] = y1 + b2v;
            }
        }
    }
}

extern "C" void kernel_launch(void* const* d_in, const int* in_sizes, int n_in,
                              void* d_out, int out_size)
{
    const float* x  = (const float*)d_in[0];  // (8, 64, 2048)
    const float* W1 = (const float*)d_in[1];  // (9, 128)
    const float* b1 = (const float*)d_in[2];  // (128,)
    const float* W2 = (const float*)d_in[3];  // (128, 1)
    const float* b2 = (const float*)d_in[4];  // (1,)
    float* out = (float*)d_out;               // (8, 64, 2048)

    simconv1d_mma<<<8 * 64 * 2, TPB>>>(x, W1, b1, W2, b2, out);
}

// round 12
// speedup vs baseline: 1.9307x; 1.3756x over previous
#include <cuda_runtime.h>
#include <cstdint>

#define LROW 2048
#define HALF 1024         // outputs per CTA (row split in 2)
#define HID  128
#define TPB  128          // 4 warps
#define NPASS 16          // 16 passes x 64 outputs = 1024 per CTA
#define PCH  4            // passes per chunk
#define XS_LEN 1040       // 4 halo + 1024 + 4 halo + pad
#define W1S 136           // padded row stride (136 % 32 == 8 -> conflict-free)

typedef unsigned long long u64;

__device__ __forceinline__ uint32_t to_tf32(float v) {
    uint32_t r;
    asm("cvt.rna.tf32.f32 %0, %1;" : "=r"(r) : "f"(v));
    return r;
}

__device__ __forceinline__ void mma_tf32(
    float& d0, float& d1, float& d2, float& d3,
    uint32_t a0, uint32_t a1, uint32_t a2, uint32_t a3,
    uint32_t b0, uint32_t b1,
    float c0, float c1, float c2, float c3)
{
    asm("mma.sync.aligned.m16n8k8.row.col.f32.tf32.tf32.f32 "
        "{%0,%1,%2,%3}, {%4,%5,%6,%7}, {%8,%9}, {%10,%11,%12,%13};"
        : "=f"(d0), "=f"(d1), "=f"(d2), "=f"(d3)
        : "r"(a0), "r"(a1), "r"(a2), "r"(a3),
          "r"(b0), "r"(b1),
          "f"(c0), "f"(c1), "f"(c2), "f"(c3));
}

__global__ __launch_bounds__(TPB, 5)   // 102-reg cap -> 5 CTAs/SM
void simconv1d_mma(const float* __restrict__ x,
                   const float* __restrict__ W1,
                   const float* __restrict__ b1,
                   const float* __restrict__ W2,
                   const float* __restrict__ b2,
                   float* __restrict__ out)
{
    __shared__ __align__(16) uint32_t xs[XS_LEN];     // tf32 padded half-row
    __shared__ __align__(16) uint32_t w1s[8 * W1S];   // tf32, K-rows 0..7 only
    __shared__ __align__(8)  float b1s[HID];
    __shared__ __align__(8)  float w8s[HID];          // W1 row 8 (fp32)
    __shared__ __align__(8)  float w2s[HID];

    const int row  = blockIdx.x >> 1;          // b*64 + h
    const int h0   = (blockIdx.x & 1) * HALF;  // output offset within row
    const int tid  = threadIdx.x;
    const float* xr = x + (size_t)row * LROW;

    // Stage padded x segment (tf32). xs[j] corresponds to x[h0 + j - 4].
    for (int i = tid; i < HALF + 8; i += TPB) {
        const int gidx = h0 + i - 4;
        uint32_t v = 0u;
        if (gidx >= 0 && gidx < LROW) v = to_tf32(xr[gidx]);
        xs[i] = v;
    }
    // Stage W1 K-rows 0..7 (tf32) for the MMA; cols >= 128 zero-padded.
    for (int i = tid; i < 8 * W1S; i += TPB) {
        int r = i / W1S, c = i % W1S;
        w1s[i] = (c < HID) ? to_tf32(W1[r * HID + c]) : 0u;
    }
    if (tid < HID) {
        b1s[tid] = b1[tid];
        w8s[tid] = W1[8 * HID + tid];   // tap-8 row, full fp32
        w2s[tid] = W2[tid];
    }
    __syncthreads();

    const int lane = tid & 31;
    const int warp = tid >> 5;
    const int g = lane >> 2;      // groupID (row within fragment)
    const int t = lane & 3;       // threadID_in_group
    const float b2v = b2[0];
    float* orow = out + (size_t)row * LROW + h0;

    #pragma unroll 1
    for (int pc = 0; pc < NPASS / PCH; pc++) {
        int o0p[PCH];
        uint32_t A[PCH][4];
        float x8a[PCH], x8b[PCH];     // tap-8 x values for rows g, g+8
        float yA[PCH], yB[PCH];       // scalar accumulators (rows g, g+8)
        #pragma unroll
        for (int q = 0; q < PCH; q++) {
            o0p[q] = (pc * PCH + q) * 64 + warp * 16;   // local to half-row
            const int base = o0p[q] + g + t;
            // Toeplitz A (K=8): a0=A[g][t], a1=A[g+8][t], a2=A[g][t+4], a3=A[g+8][t+4]
            A[q][0] = xs[base];
            A[q][1] = xs[base + 8];
            A[q][2] = xs[base + 4];
            A[q][3] = xs[base + 12];
            // tap-8 inputs (no t offset): x[o0+m+8] for m = g, g+8
            x8a[q] = __uint_as_float(xs[o0p[q] + g + 8]);
            x8b[q] = __uint_as_float(xs[o0p[q] + g + 16]);
            yA[q] = 0.0f;
            yB[q] = 0.0f;
        }

        #pragma unroll 2
        for (int n = 0; n < 16; n++) {
            const int nc = n * 8;
            // B fragments (col-major 8x8): b0 = W[t][nc+g], b1 = W[t+4][nc+g]
            const uint32_t bk0 = w1s[t * W1S + nc + g];
            const uint32_t bk1 = w1s[(t + 4) * W1S + nc + g];

            const float2 bias = *(const float2*)&b1s[nc + 2 * t];
            const float2 w8v  = *(const float2*)&w8s[nc + 2 * t];
            const float2 w2v  = *(const float2*)&w2s[nc + 2 * t];

            #pragma unroll
            for (int q = 0; q < PCH; q++) {
                // Fold tap-8 + bias into the C operand: c = x8*w8 + b1.
                const float c0 = fmaf(x8a[q], w8v.x, bias.x);
                const float c1 = fmaf(x8a[q], w8v.y, bias.y);
                const float c2 = fmaf(x8b[q], w8v.x, bias.x);
                const float c3 = fmaf(x8b[q], w8v.y, bias.y);

                float d0, d1, d2, d3;
                mma_tf32(d0, d1, d2, d3,
                         A[q][0], A[q][1], A[q][2], A[q][3],
                         bk0, bk1,
                         c0, c1, c2, c3);

                // relu + projection with W2 (scalar, fma pipe).
                yA[q] = fmaf(fmaxf(d0, 0.0f), w2v.x, yA[q]);
                yA[q] = fmaf(fmaxf(d1, 0.0f), w2v.y, yA[q]);
                yB[q] = fmaf(fmaxf(d2, 0.0f), w2v.x, yB[q]);
                yB[q] = fmaf(fmaxf(d3, 0.0f), w2v.y, yB[q]);
            }
        }

        #pragma unroll
        for (int q = 0; q < PCH; q++) {
            float y0 = yA[q];
            float y1 = yB[q];
            y0 += __shfl_xor_sync(0xffffffffu, y0, 1);
            y0 += __shfl_xor_sync(0xffffffffu, y0, 2);
            y1 += __shfl_xor_sync(0xffffffffu, y1, 1);
            y1 += __shfl_xor_sync(0xffffffffu, y1, 2);
            if (t == 0) {
                orow[o0p[q] + g]     = y0 + b2v;
                orow[o0p[q] + g + 8] = y1 + b2v;
            }
        }
    }
}

extern "C" void kernel_launch(void* const* d_in, const int* in_sizes, int n_in,
                              void* d_out, int out_size)
{
    const float* x  = (const float*)d_in[0];  // (8, 64, 2048)
    const float* W1 = (const float*)d_in[1];  // (9, 128)
    const float* b1 = (const float*)d_in[2];  // (128,)
    const float* W2 = (const float*)d_in[3];  // (128, 1)
    const float* b2 = (const float*)d_in[4];  // (1,)
    float* out = (float*)d_out;               // (8, 64, 2048)

    simconv1d_mma<<<8 * 64 * 2, TPB>>>(x, W1, b1, W2, b2, out);
}